// round 10
// baseline (speedup 1.0000x reference)
#include <cuda_runtime.h>
#include <cuda_fp16.h>
#include <cstdint>
#include <cstddef>

#define DEVINL __device__ __forceinline__

constexpr int MROWS = 16384;
constexpr int KTOT  = 1024;
constexpr int NCOLS = 1024;

constexpr int BM = 128, BN = 128, BK = 64;
constexpr int STAGES = 3;
constexpr int TPB = 256;
constexpr int NCHUNK = KTOT / BK;               // 16
constexpr int NPANEL = MROWS / BM;              // 128

constexpr int A_BYTES = BM * BK * 2;            // 16 KB
constexpr int B_BYTES = BN * BK * 2;            // 16 KB
constexpr int STAGE_BYTES = A_BYTES + B_BYTES;  // 32 KB
constexpr int SMEM_TOTAL = STAGES * STAGE_BYTES; // 96 KB (x2 CTAs = 192 KB/SM)

// Static device scratch (allocation-free rule)
__device__ __half g_ah[(size_t)MROWS * KTOT];   // A converted to fp16 (by GEMM CTAs)
__device__ __half g_wt[(size_t)NCOLS * KTOT];   // W quantized, [n][k] K-major
__device__ unsigned g_af[NPANEL * NCHUNK];      // A chunk ready flags (zero-init)

// ---------------------------------------------------------------- helpers
DEVINL uint32_t smem_u32(const void* p) {
    uint32_t r;
    asm("{ .reg .u64 t; cvta.to.shared.u64 t, %1; cvt.u32.u64 %0, t; }"
        : "=r"(r) : "l"(p));
    return r;
}
DEVINL uint32_t swz(uint32_t off) { return off ^ ((off >> 3) & 0x70); }
DEVINL void cp_async16(uint32_t s, const void* g) {
    asm volatile("cp.async.cg.shared.global [%0], [%1], 16;"
                 :: "r"(s), "l"(g) : "memory");
}
DEVINL void cp_commit() { asm volatile("cp.async.commit_group;" ::: "memory"); }
template <int N> DEVINL void cp_wait() {
    asm volatile("cp.async.wait_group %0;" :: "n"(N) : "memory");
}
DEVINL void ldsm_x4(uint32_t* r, uint32_t addr) {
    asm volatile("ldmatrix.sync.aligned.m8n8.x4.shared.b16 {%0,%1,%2,%3}, [%4];"
                 : "=r"(r[0]), "=r"(r[1]), "=r"(r[2]), "=r"(r[3]) : "r"(addr));
}
DEVINL void mma16816(float* c, const uint32_t* a, const uint32_t* b) {
    asm volatile(
        "mma.sync.aligned.m16n8k16.row.col.f32.f16.f16.f32 "
        "{%0,%1,%2,%3}, {%4,%5,%6,%7}, {%8,%9}, {%0,%1,%2,%3};"
        : "+f"(c[0]), "+f"(c[1]), "+f"(c[2]), "+f"(c[3])
        : "r"(a[0]), "r"(a[1]), "r"(a[2]), "r"(a[3]), "r"(b[0]), "r"(b[1]));
}
DEVINL uint32_t pack_half2(float x, float y) {
    __half2 h = __floats2half2_rn(x, y);
    return *reinterpret_cast<uint32_t*>(&h);
}
DEVINL unsigned flag_ld(const unsigned* p) {
    unsigned v;
    asm volatile("ld.acquire.gpu.global.u32 %0, [%1];" : "=r"(v) : "l"(p) : "memory");
    return v;
}
DEVINL void flag_st(unsigned* p) {
    asm volatile("st.release.gpu.global.u32 [%0], 1;" :: "l"(p) : "memory");
}
DEVINL void flag_spin(const unsigned* p) {
    if (flag_ld(p)) return;
    while (!flag_ld(p)) __nanosleep(128);
}

// -------------------------------------------- W quantize + transpose (tiny)
__global__ void quant_w_kernel(const float* __restrict__ w) {
    __shared__ __half tile[32][33];
    const int n0 = (blockIdx.x & 31) * 32;
    const int k0 = (blockIdx.x >> 5) * 32;
    const int tx = threadIdx.x & 31;
    const int ty = threadIdx.x >> 5;
    #pragma unroll
    for (int i = ty; i < 32; i += 8) {
        float x = w[(size_t)(k0 + i) * NCOLS + n0 + tx];
        x = fminf(fmaxf(x, -0.5f), 0.5f);     // clip [-1+delta, 1-delta]
        float y = rintf(x * 2.0f) * 0.5f;     // round-half-even, step 0.5
        tile[i][tx] = __float2half_rn(y);     // exact in fp16
    }
    __syncthreads();
    #pragma unroll
    for (int i = ty; i < 32; i += 8)
        g_wt[(size_t)(n0 + i) * KTOT + k0 + tx] = tile[tx][i];
}

// ------------------------------------------------------------- main GEMM
// R4 mainloop (proven 84.6us) + in-kernel A conversion via ready-flags.
__global__ void __launch_bounds__(TPB, 2)
gemm_hmma_kernel(const float* __restrict__ Afp32, float* __restrict__ C) {
    extern __shared__ char smem[];
    const uint32_t sb = smem_u32(smem);
    const int tid  = threadIdx.x;
    const int lane = tid & 31;
    const int wid  = tid >> 5;
    const int warpM = wid & 3;
    const int warpN = wid >> 2;

    const int mPanel = blockIdx.y;
    const int m0 = mPanel * BM;
    const int n0 = blockIdx.x * BN;

    // ---- converter prologue: this CTA converts A chunks {n, n+8} of its panel
    {
        const int nIdx = blockIdx.x;             // 0..7
        const float* As = Afp32 + (size_t)m0 * KTOT;
        __half*      Ad = g_ah  + (size_t)m0 * KTOT;
        const int r0   = tid >> 4;               // 0..15
        const int col4 = (tid & 15) * 4;         // float4 column within chunk
        #pragma unroll
        for (int cc = 0; cc < 2; cc++) {
            const int kc = nIdx + cc * 8;
            const int c0 = kc * BK + col4;
            #pragma unroll
            for (int p = 0; p < 8; p++) {
                const int row = r0 + p * 16;
                float4 v = *reinterpret_cast<const float4*>(
                    As + (size_t)row * KTOT + c0);
                *reinterpret_cast<uint2*>(Ad + (size_t)row * KTOT + c0) =
                    make_uint2(pack_half2(v.x, v.y), pack_half2(v.z, v.w));
            }
            __threadfence();                     // each thread's STGs visible gpu-wide
            __syncthreads();                     // all threads fenced
            if (tid == 0) flag_st(&g_af[mPanel * NCHUNK + kc]);
        }
    }

    const char* aG = (const char*)(g_ah + (size_t)m0 * KTOT);
    const char* bG = (const char*)(g_wt + (size_t)n0 * KTOT);

    const int lr = tid >> 3;
    const int lc = (tid & 7) * 16;
    const uint32_t ld_sw0 = swz(lr * 128 + lc);

    auto load_stage = [&](int kc, int s) {
        const uint32_t aS = sb + s * STAGE_BYTES;
        const uint32_t bS = aS + A_BYTES;
        const char* ag = aG + (size_t)lr * (KTOT * 2) + kc * (BK * 2) + lc;
        const char* bg = bG + (size_t)lr * (KTOT * 2) + kc * (BK * 2) + lc;
        #pragma unroll
        for (int it = 0; it < 4; it++) {
            const uint32_t sw = ld_sw0 + it * 32 * 128;
            cp_async16(aS + sw, ag + (size_t)it * 32 * KTOT * 2);
            cp_async16(bS + sw, bg + (size_t)it * 32 * KTOT * 2);
        }
    };

    uint32_t aBase[2], bBase[4];
    #pragma unroll
    for (int mi = 0; mi < 2; mi++) {
        const int row = warpM * 32 + mi * 16 + (lane & 15);
        const int ko  = (lane >> 4) * 8;
        aBase[mi] = swz(row * 128 + ko * 2);
    }
    #pragma unroll
    for (int nj = 0; nj < 4; nj++) {
        const int row = warpN * 64 + nj * 16 + ((lane >> 4) << 3) + (lane & 7);
        const int ko  = ((lane >> 3) & 1) * 8;
        bBase[nj] = swz(row * 128 + ko * 2) + A_BYTES;
    }

    // prologue: wait for chunks 0,1 (self/peer-converted), then load
    #pragma unroll
    for (int s = 0; s < STAGES - 1; s++) {
        flag_spin(&g_af[mPanel * NCHUNK + s]);
        load_stage(s, s);
        cp_commit();
    }

    float acc[2][8][4] = {};

    for (int kc = 0; kc < NCHUNK; kc++) {
        cp_wait<1>();          // stage kc's group complete (this thread)
        __syncthreads();       // publish; also: all warps done computing kc-1

        // early flag probe for kc+2 — latency hidden under the ki compute
        const int kn = kc + 2;
        unsigned rdy = 1;
        if (kn < NCHUNK) rdy = flag_ld(&g_af[mPanel * NCHUNK + kn]);

        const uint32_t stS = sb + (kc % STAGES) * STAGE_BYTES;

        #pragma unroll
        for (int ki = 0; ki < BK / 16; ki++) {
            const uint32_t kOff = ki * 32;
            uint32_t afr[2][4], bfr[4][4];
            #pragma unroll
            for (int mi = 0; mi < 2; mi++)
                ldsm_x4(afr[mi], stS + (aBase[mi] ^ kOff));
            #pragma unroll
            for (int nj = 0; nj < 4; nj++)
                ldsm_x4(bfr[nj], stS + (bBase[nj] ^ kOff));
            #pragma unroll
            for (int mi = 0; mi < 2; mi++)
                #pragma unroll
                for (int nj = 0; nj < 8; nj++)
                    mma16816(acc[mi][nj], afr[mi], &bfr[nj >> 1][(nj & 1) * 2]);
        }

        // issue next-stage loads after compute (still ~1 chunk-time of cover)
        if (kn < NCHUNK) {
            if (!rdy) flag_spin(&g_af[mPanel * NCHUNK + kn]);
            load_stage(kn, kn % STAGES);
        }
        cp_commit();           // unconditional: uniform group accounting
    }

    // ---- epilogue
    float* cBase = C + (size_t)(m0 + warpM * 32) * NCOLS + n0 + warpN * 64;
    const int cr = lane >> 2;
    const int cc = (lane & 3) * 2;
    #pragma unroll
    for (int mi = 0; mi < 2; mi++) {
        #pragma unroll
        for (int nj = 0; nj < 8; nj++) {
            float* p0 = cBase + (size_t)(mi * 16 + cr) * NCOLS + nj * 8 + cc;
            float* p1 = p0 + 8 * NCOLS;
            *reinterpret_cast<float2*>(p0) = make_float2(acc[mi][nj][0], acc[mi][nj][1]);
            *reinterpret_cast<float2*>(p1) = make_float2(acc[mi][nj][2], acc[mi][nj][3]);
        }
    }
}

// ---------------------------------------------------------------- launch
extern "C" void kernel_launch(void* const* d_in, const int* in_sizes, int n_in,
                              void* d_out, int out_size) {
    (void)in_sizes; (void)n_in; (void)out_size;
    const float* A = (const float*)d_in[0];   // [16384, 1024] fp32
    const float* W = (const float*)d_in[1];   // [1024, 1024] fp32
    float* C = (float*)d_out;                 // [16384, 1024] fp32

    quant_w_kernel<<<(NCOLS / 32) * (KTOT / 32), 256>>>(W);

    cudaFuncSetAttribute(gemm_hmma_kernel,
                         cudaFuncAttributeMaxDynamicSharedMemorySize, SMEM_TOTAL);
    gemm_hmma_kernel<<<dim3(NCOLS / BN, MROWS / BM), TPB, SMEM_TOTAL>>>(A, C);
}